// round 1
// baseline (speedup 1.0000x reference)
#include <cuda_runtime.h>
#include <math.h>

#define N 4096
#define D 512
#define NN (N * N)

// log2-domain scale: (1/EPS) * log2(e)
#define KSCALE 14.4269504088896340736f
// EPS * ln2 / N
#define OUT_SCALE (0.1 * 0.69314718055994530942 / 4096.0)

// ---------------- device scratch (no allocations allowed) ----------------
__device__ float d_Cxy[NN];
__device__ float d_Cyx[NN];
__device__ float d_Cxx[NN];
__device__ float d_Cyy[NN];
__device__ float d_xsq[N];
__device__ float d_ysq[N];
__device__ float d_F[3][N];
__device__ float d_G[3][N];

__device__ __forceinline__ float ex2f(float x) {
    float y;
    asm("ex2.approx.ftz.f32 %0, %1;" : "=f"(y) : "f"(x));
    return y;
}

// ---------------- row sum-of-squares ----------------
__global__ void rowsq_kernel(const float* __restrict__ X, float* __restrict__ out) {
    int row = blockIdx.x * 8 + threadIdx.y;
    const float* xr = X + (size_t)row * D;
    float s = 0.f;
    for (int k = threadIdx.x; k < D; k += 32) {
        float v = __ldg(xr + k);
        s = fmaf(v, v, s);
    }
    #pragma unroll
    for (int off = 16; off > 0; off >>= 1)
        s += __shfl_down_sync(0xffffffffu, s, off);
    if (threadIdx.x == 0) out[row] = s;
}

// ---------------- cost GEMM: Cout[i][j] = clip(a2[i]+b2[j]-2*dot,0,1e6)*KSCALE ----
#define GBM 128
#define GBN 128
#define GBK 8
__global__ __launch_bounds__(256) void gemm_cost_kernel(
    const float* __restrict__ A, const float* __restrict__ B,
    const float* __restrict__ a2, const float* __restrict__ b2,
    float* __restrict__ Cout)
{
    __shared__ float As[GBK][GBM];
    __shared__ float Bs[GBK][GBN];
    const int tid  = threadIdx.x;
    const int irow = tid >> 1;
    const int icol = (tid & 1) * 4;
    const int trow = (tid >> 4) * 8;
    const int tcol = (tid & 15) * 8;

    const float* Aptr = A + (size_t)(blockIdx.y * GBM + irow) * D + icol;
    const float* Bptr = B + (size_t)(blockIdx.x * GBN + irow) * D + icol;

    float acc[8][8];
    #pragma unroll
    for (int i = 0; i < 8; i++)
        #pragma unroll
        for (int j = 0; j < 8; j++) acc[i][j] = 0.f;

    for (int k0 = 0; k0 < D; k0 += GBK) {
        float4 av = *(const float4*)(Aptr + k0);
        float4 bv = *(const float4*)(Bptr + k0);
        __syncthreads();
        As[icol + 0][irow] = av.x; As[icol + 1][irow] = av.y;
        As[icol + 2][irow] = av.z; As[icol + 3][irow] = av.w;
        Bs[icol + 0][irow] = bv.x; Bs[icol + 1][irow] = bv.y;
        Bs[icol + 2][irow] = bv.z; Bs[icol + 3][irow] = bv.w;
        __syncthreads();
        #pragma unroll
        for (int k = 0; k < GBK; k++) {
            float ar[8], br[8];
            #pragma unroll
            for (int i = 0; i < 8; i++) ar[i] = As[k][trow + i];
            #pragma unroll
            for (int j = 0; j < 8; j++) br[j] = Bs[k][tcol + j];
            #pragma unroll
            for (int i = 0; i < 8; i++)
                #pragma unroll
                for (int j = 0; j < 8; j++)
                    acc[i][j] = fmaf(ar[i], br[j], acc[i][j]);
        }
    }

    const int gi = blockIdx.y * GBM + trow;
    const int gj = blockIdx.x * GBN + tcol;
    #pragma unroll
    for (int i = 0; i < 8; i++) {
        float ai = __ldg(a2 + gi + i);
        float* crow = Cout + (size_t)(gi + i) * N + gj;
        #pragma unroll
        for (int j = 0; j < 8; j++) {
            float c = ai + __ldg(b2 + gj + j) - 2.0f * acc[i][j];
            c = fminf(fmaxf(c, 0.0f), 1.0e6f);
            crow[j] = c * KSCALE;
        }
    }
}

// ---------------- transpose (Cyx = Cxy^T) ----------------
__global__ void transpose_kernel(const float* __restrict__ in, float* __restrict__ out) {
    __shared__ float tile[32][33];
    int x = blockIdx.x * 32 + threadIdx.x;
    int y = blockIdx.y * 32 + threadIdx.y;
    #pragma unroll
    for (int r = 0; r < 32; r += 8)
        tile[threadIdx.y + r][threadIdx.x] = in[(size_t)(y + r) * N + x];
    __syncthreads();
    int xo = blockIdx.y * 32 + threadIdx.x;
    int yo = blockIdx.x * 32 + threadIdx.y;
    #pragma unroll
    for (int r = 0; r < 32; r += 8)
        out[(size_t)(yo + r) * N + xo] = tile[threadIdx.x][threadIdx.y + r];
}

// ---------------- potential init ----------------
__global__ void init_pot_kernel() {
    int i = blockIdx.x * 256 + threadIdx.x;
    if (i < 3 * N) {
        (&d_F[0][0])[i] = 0.f;
        (&d_G[0][0])[i] = 0.f;
    }
}

// ---------------- one half-iteration: row-wise log2-sum-exp2 ----------------
__device__ __forceinline__ void lse_up(float& m, float& s, float a) {
    if (a <= m) {
        s += ex2f(a - m);
    } else {
        s = fmaf(s, ex2f(m - a), 1.0f);
        m = a;
    }
}

__global__ __launch_bounds__(256) void lse_pass_kernel(int phase) {
    const int p = blockIdx.y;   // 0=xy, 1=xx, 2=yy
    const float* M;
    if (p == 0) M = (phase == 0) ? d_Cxy : d_Cyx;
    else if (p == 1) M = d_Cxx;
    else M = d_Cyy;
    const float* vin  = (phase == 0) ? d_G[p] : d_F[p];
    float* vout       = (phase == 0) ? d_F[p] : d_G[p];

    const int row = blockIdx.x;
    const float* Mr = M + (size_t)row * N;
    const int t4 = threadIdx.x * 4;

    float4 mv[4], vv[4];
    #pragma unroll
    for (int k = 0; k < 4; k++) {
        int j = t4 + k * 1024;
        mv[k] = *(const float4*)(Mr + j);
        vv[k] = *(const float4*)(vin + j);
    }

    float m = __int_as_float(0xff800000);  // -inf
    float s = 0.f;
    #pragma unroll
    for (int k = 0; k < 4; k++) {
        lse_up(m, s, vv[k].x - mv[k].x);
        lse_up(m, s, vv[k].y - mv[k].y);
        lse_up(m, s, vv[k].z - mv[k].z);
        lse_up(m, s, vv[k].w - mv[k].w);
    }

    __shared__ float sm[256], ss[256];
    sm[threadIdx.x] = m;
    ss[threadIdx.x] = s;
    __syncthreads();
    for (int off = 128; off > 0; off >>= 1) {
        if (threadIdx.x < off) {
            float m1 = sm[threadIdx.x], s1 = ss[threadIdx.x];
            float m2 = sm[threadIdx.x + off], s2 = ss[threadIdx.x + off];
            float mm = fmaxf(m1, m2);
            sm[threadIdx.x] = mm;
            ss[threadIdx.x] = fmaf(s1, ex2f(m1 - mm), s2 * ex2f(m2 - mm));
        }
        __syncthreads();
    }
    if (threadIdx.x == 0)
        vout[row] = 12.0f - (sm[0] + log2f(ss[0]));
}

// ---------------- final scalar reduce ----------------
__global__ __launch_bounds__(256) void final_reduce_kernel(float* __restrict__ out) {
    __shared__ double sh[3][256];
    const int tid = threadIdx.x;
    double acc0 = 0.0, acc1 = 0.0, acc2 = 0.0;
    for (int j = tid; j < N; j += 256) {
        acc0 += (double)d_F[0][j] + (double)d_G[0][j];
        acc1 += (double)d_F[1][j] + (double)d_G[1][j];
        acc2 += (double)d_F[2][j] + (double)d_G[2][j];
    }
    sh[0][tid] = acc0; sh[1][tid] = acc1; sh[2][tid] = acc2;
    __syncthreads();
    for (int off = 128; off > 0; off >>= 1) {
        if (tid < off) {
            sh[0][tid] += sh[0][tid + off];
            sh[1][tid] += sh[1][tid + off];
            sh[2][tid] += sh[2][tid + off];
        }
        __syncthreads();
    }
    if (tid == 0) {
        double Sdiff = sh[0][0] - 0.5 * (sh[1][0] + sh[2][0]);
        double val = Sdiff * OUT_SCALE;
        out[0] = (float)(val > 0.0 ? val : 0.0);
    }
}

// ---------------- launch ----------------
extern "C" void kernel_launch(void* const* d_in, const int* in_sizes, int n_in,
                              void* d_out, int out_size)
{
    const float* x = (const float*)d_in[0];
    const float* y = (const float*)d_in[1];
    float* out = (float*)d_out;

    float *Cxy, *Cyx, *Cxx, *Cyy, *xsq, *ysq;
    cudaGetSymbolAddress((void**)&Cxy, d_Cxy);
    cudaGetSymbolAddress((void**)&Cyx, d_Cyx);
    cudaGetSymbolAddress((void**)&Cxx, d_Cxx);
    cudaGetSymbolAddress((void**)&Cyy, d_Cyy);
    cudaGetSymbolAddress((void**)&xsq, d_xsq);
    cudaGetSymbolAddress((void**)&ysq, d_ysq);

    dim3 rsBlock(32, 8);
    rowsq_kernel<<<N / 8, rsBlock>>>(x, xsq);
    rowsq_kernel<<<N / 8, rsBlock>>>(y, ysq);

    dim3 gGrid(N / GBN, N / GBM);
    gemm_cost_kernel<<<gGrid, 256>>>(x, y, xsq, ysq, Cxy);
    gemm_cost_kernel<<<gGrid, 256>>>(x, x, xsq, xsq, Cxx);
    gemm_cost_kernel<<<gGrid, 256>>>(y, y, ysq, ysq, Cyy);

    dim3 tBlock(32, 8);
    dim3 tGrid(N / 32, N / 32);
    transpose_kernel<<<tGrid, tBlock>>>(Cxy, Cyx);

    init_pot_kernel<<<(3 * N + 255) / 256, 256>>>();

    dim3 lGrid(N, 3);
    for (int it = 0; it < 50; it++) {
        lse_pass_kernel<<<lGrid, 256>>>(0);
        lse_pass_kernel<<<lGrid, 256>>>(1);
    }

    final_reduce_kernel<<<1, 256>>>(out);
}